// round 6
// baseline (speedup 1.0000x reference)
#include <cuda_runtime.h>
#include <math.h>
#include <stdint.h>
#include <mma.h>

using namespace nvcuda;

#define NTOK 8192
#define DMODEL 1024
#define FFN 4096
#define NEXP 8
#define NPAIR (NTOK*2)
#define LB_COEF 0.01f
#define Z_COEF 0.001f

// WMMA GEMM tiling
#define BM 128
#define BN 64
#define BK 32
#define ASTR 36     // A smem row stride (floats): 144B = 9*16 ✓
#define BSTR 68     // B smem row stride (floats): 272B = 17*16 ✓

// ---------------- device scratch (R1-proven footprint) ----------------
__device__ float g_H[(size_t)(NPAIR + BM) * FFN];   // hidden per pair slot
__device__ float g_probs[NTOK * NEXP];
__device__ float g_zsq[NTOK];
__device__ int   g_te[NTOK * 2];
__device__ float g_tw[NTOK * 2];
__device__ int   g_pairTok[NPAIR + BM];
__device__ float g_pairW[NPAIR + BM];
__device__ int   g_cnt[NEXP];
__device__ int   g_off[NEXP];
__device__ int   g_cursor[NEXP];
__device__ int   g_useMMA;

// ---------------- helpers ----------------
__device__ __forceinline__ float rna_tf32(float x) {
    float r; asm("cvt.rna.tf32.f32 %0, %1;" : "=f"(r) : "f"(x)); return r;
}

// ---------------- kernel 0: zero y + counters ----------------
__global__ void k_zero(float* __restrict__ y) {
    size_t i = (size_t)blockIdx.x * blockDim.x + threadIdx.x;
    const size_t n4 = (size_t)NTOK * DMODEL / 4;
    float4 z = make_float4(0.f, 0.f, 0.f, 0.f);
    for (; i < n4; i += (size_t)gridDim.x * blockDim.x)
        reinterpret_cast<float4*>(y)[i] = z;
    if (blockIdx.x == 0 && threadIdx.x < NEXP) g_cnt[threadIdx.x] = 0;
}

// ---------------- MMA self-test: does tf32 WMMA produce correct results? ----------------
__global__ void k_mmatest() {
    __shared__ __align__(16) float a[16 * ASTR];
    __shared__ __align__(16) float b[8 * BSTR];
    __shared__ __align__(16) float c[16 * 20];
    int tid = threadIdx.x;
    for (int i = tid; i < 16 * ASTR; i += 32) a[i] = 1.0f;
    for (int i = tid; i < 8 * BSTR; i += 32) b[i] = 1.0f;
    __syncwarp();
    wmma::fragment<wmma::matrix_a, 16, 16, 8, wmma::precision::tf32, wmma::row_major> fa;
    wmma::fragment<wmma::matrix_b, 16, 16, 8, wmma::precision::tf32, wmma::row_major> fb;
    wmma::fragment<wmma::accumulator, 16, 16, 8, float> fc;
    wmma::fill_fragment(fc, 0.f);
    wmma::load_matrix_sync(fa, a, ASTR);
    wmma::load_matrix_sync(fb, b, BSTR);
    wmma::mma_sync(fc, fa, fb, fc);
    wmma::store_matrix_sync(c, fc, 20, wmma::mem_row_major);
    __syncwarp();
    if (tid == 0) {
        int ok = 1;
        for (int r = 0; r < 16; r++)
            for (int n = 0; n < 16; n++)
                if (fabsf(c[r * 20 + n] - 8.0f) > 0.01f) ok = 0;
        g_useMMA = ok;
    }
}

// ---------------- kernel 1: router ----------------
__global__ void __launch_bounds__(256) k_router(const float* __restrict__ x,
                                                const float* __restrict__ Wr) {
    __shared__ float sWr[DMODEL * NEXP];
    int tid = threadIdx.x;
    for (int i = tid * 4; i < DMODEL * NEXP; i += blockDim.x * 4)
        *reinterpret_cast<float4*>(&sWr[i]) = *reinterpret_cast<const float4*>(&Wr[i]);
    __syncthreads();

    int warp = tid >> 5, lane = tid & 31;
    int t = blockIdx.x * 8 + warp;
    if (t >= NTOK) return;

    float acc[NEXP];
#pragma unroll
    for (int e = 0; e < NEXP; e++) acc[e] = 0.f;
    const float* xr = x + (size_t)t * DMODEL;
    for (int d = lane; d < DMODEL; d += 32) {
        float xv = xr[d];
#pragma unroll
        for (int e = 0; e < NEXP; e++) acc[e] += xv * sWr[d * NEXP + e];
    }
#pragma unroll
    for (int e = 0; e < NEXP; e++)
        for (int o = 16; o; o >>= 1) acc[e] += __shfl_xor_sync(0xffffffff, acc[e], o);

    if (lane == 0) {
        float v0 = -1e30f; int i0 = 0;
#pragma unroll
        for (int e = 0; e < NEXP; e++) if (acc[e] > v0) { v0 = acc[e]; i0 = e; }
        float v1 = -1e30f; int i1 = 0;
#pragma unroll
        for (int e = 0; e < NEXP; e++) if (e != i0 && acc[e] > v1) { v1 = acc[e]; i1 = e; }

        float e1v = expf(v1 - v0);
        float inv2 = 1.f / (1.f + e1v);

        float se = 0.f, pr[NEXP];
#pragma unroll
        for (int e = 0; e < NEXP; e++) { pr[e] = expf(acc[e] - v0); se += pr[e]; }
        float invs = 1.f / se;
#pragma unroll
        for (int e = 0; e < NEXP; e++) g_probs[t * NEXP + e] = pr[e] * invs;
        float z = v0 + logf(se);
        g_zsq[t] = z * z;

        g_te[t * 2] = i0; g_te[t * 2 + 1] = i1;
        g_tw[t * 2] = inv2; g_tw[t * 2 + 1] = e1v * inv2;
        atomicAdd(&g_cnt[i0], 1);
        atomicAdd(&g_cnt[i1], 1);
    }
}

// ---------------- kernel 2: reductions + aux + offsets ----------------
__global__ void __launch_bounds__(1024) k_finalize(float* __restrict__ out) {
    __shared__ float red[1024];
    __shared__ float simp[NEXP];
    __shared__ float szsq;
    int tid = threadIdx.x;

    float s[NEXP];
#pragma unroll
    for (int e = 0; e < NEXP; e++) s[e] = 0.f;
    float zs = 0.f;
    for (int t = tid; t < NTOK; t += 1024) {
#pragma unroll
        for (int e = 0; e < NEXP; e++) s[e] += g_probs[t * NEXP + e];
        zs += g_zsq[t];
    }
    for (int e = 0; e < NEXP; e++) {
        red[tid] = s[e]; __syncthreads();
        for (int o = 512; o > 0; o >>= 1) { if (tid < o) red[tid] += red[tid + o]; __syncthreads(); }
        if (tid == 0) simp[e] = red[0] / (float)NTOK;
        __syncthreads();
    }
    red[tid] = zs; __syncthreads();
    for (int o = 512; o > 0; o >>= 1) { if (tid < o) red[tid] += red[tid + o]; __syncthreads(); }
    if (tid == 0) szsq = red[0];
    __syncthreads();

    if (tid == 0) {
        float lb = 0.f;
#pragma unroll
        for (int e = 0; e < NEXP; e++) lb += simp[e] * simp[e];
        lb *= (float)NEXP * LB_COEF;
        float aux = lb + (szsq / (float)NTOK) * Z_COEF;

        float* tail = out + (size_t)NTOK * DMODEL;
        int tot = 0;
        for (int e = 0; e < NEXP; e++) tot += g_cnt[e];
        float denom = fmaxf((float)tot, 1.f);
        for (int e = 0; e < NEXP; e++) {
            tail[e] = (float)g_cnt[e];
            tail[NEXP + e] = (float)g_cnt[e] / denom;
        }
        tail[2 * NEXP] = aux;

        int o = 0;
        for (int e = 0; e < NEXP; e++) { g_off[e] = o; g_cursor[e] = o; o += g_cnt[e]; }
    }
}

// ---------------- kernel 3: scatter ----------------
__global__ void k_scatter() {
    int t = blockIdx.x * blockDim.x + threadIdx.x;
    if (t >= NTOK) return;
#pragma unroll
    for (int k = 0; k < 2; k++) {
        int e = g_te[t * 2 + k];
        int p = atomicAdd(&g_cursor[e], 1);
        g_pairTok[p] = t;
        g_pairW[p] = g_tw[t * 2 + k];
    }
}

// ================= WMMA tf32 path (runs iff g_useMMA == 1) =================
// FFN1: H = relu(gather(x) @ W1[e] + b1)   W1[e] is [D][F] = row-major [k][n]
// else: y += w * (H @ W2[e] + b2)          W2[e] is [F][D] = row-major [k][n]
template<int KDIM, bool FFN1>
__global__ void __launch_bounds__(256) k_wmma(const float* __restrict__ x,
                                              const float* __restrict__ W,
                                              const float* __restrict__ bias,
                                              float* __restrict__ y) {
    if (!g_useMMA) return;
    int e = blockIdx.z;
    int rows = g_cnt[e];
    int m0 = blockIdx.x * BM;
    if (m0 >= rows) return;
    int base = g_off[e];
    int n0 = blockIdx.y * BN;
    const int NT = FFN1 ? FFN : DMODEL;

    __shared__ __align__(16) float sA[BM * ASTR];   // 18432 B
    __shared__ __align__(16) float sB[BK * BSTR];   //  8704 B
    __shared__ int   stok[BM];
    __shared__ float swt[BM];

    int tid = threadIdx.x;
    if (tid < BM) {
        int r = m0 + tid;
        int rr = (r < rows) ? r : 0;
        stok[tid] = g_pairTok[base + rr];
        swt[tid]  = g_pairW[base + rr];
    }
    __syncthreads();

    const float* We = W + (size_t)e * ((size_t)DMODEL * FFN);  // row len NT
    const float* Ah = g_H + (size_t)(base + m0) * KDIM;        // GEMM2 A rows

    const int nch = KDIM / BK;
    float4 pA[4]; float4 pB[2];

    auto gload = [&](int c) {
        int k0 = c * BK;
#pragma unroll
        for (int j = 0; j < 4; j++) {
            int idx = tid + j * 256;
            int r = idx >> 3, c4 = (idx & 7) * 4;
            const float* src = FFN1
                ? &x[(size_t)stok[r] * DMODEL + k0 + c4]
                : &Ah[(size_t)r * KDIM + k0 + c4];
            pA[j] = *reinterpret_cast<const float4*>(src);
        }
#pragma unroll
        for (int j = 0; j < 2; j++) {
            int idx = tid + j * 256;
            int r = idx >> 4, c4 = (idx & 15) * 4;   // r<32 rows(k), c4<64 cols(n)
            pB[j] = *reinterpret_cast<const float4*>(&We[(size_t)(k0 + r) * NT + n0 + c4]);
        }
    };
    auto sstore = [&]() {
#pragma unroll
        for (int j = 0; j < 4; j++) {
            int idx = tid + j * 256;
            int r = idx >> 3, c4 = (idx & 7) * 4;
            float4 v = pA[j];
            v.x = rna_tf32(v.x); v.y = rna_tf32(v.y);
            v.z = rna_tf32(v.z); v.w = rna_tf32(v.w);
            *reinterpret_cast<float4*>(&sA[r * ASTR + c4]) = v;
        }
#pragma unroll
        for (int j = 0; j < 2; j++) {
            int idx = tid + j * 256;
            int r = idx >> 4, c4 = (idx & 15) * 4;
            float4 v = pB[j];
            v.x = rna_tf32(v.x); v.y = rna_tf32(v.y);
            v.z = rna_tf32(v.z); v.w = rna_tf32(v.w);
            *reinterpret_cast<float4*>(&sB[r * BSTR + c4]) = v;
        }
    };

    int lane = tid & 31, wid = tid >> 5;
    int wm = (wid & 1) * 64;      // 2 warps over M (64 rows each)
    int wn = (wid >> 1) * 16;     // 4 warps over N (16 cols each)

    wmma::fragment<wmma::accumulator, 16, 16, 8, float> acc[4];
#pragma unroll
    for (int mt = 0; mt < 4; mt++) wmma::fill_fragment(acc[mt], 0.f);

    gload(0);
    sstore();
    __syncthreads();

    for (int c = 0; c < nch; c++) {
        bool nx = (c + 1) < nch;
        if (nx) gload(c + 1);
#pragma unroll
        for (int kk = 0; kk < BK; kk += 8) {
            wmma::fragment<wmma::matrix_a, 16, 16, 8, wmma::precision::tf32,
                           wmma::row_major> fa[4];
            wmma::fragment<wmma::matrix_b, 16, 16, 8, wmma::precision::tf32,
                           wmma::row_major> fb;
#pragma unroll
            for (int mt = 0; mt < 4; mt++)
                wmma::load_matrix_sync(fa[mt], &sA[(wm + mt * 16) * ASTR + kk], ASTR);
            wmma::load_matrix_sync(fb, &sB[kk * BSTR + wn], BSTR);
#pragma unroll
            for (int mt = 0; mt < 4; mt++)
                wmma::mma_sync(acc[mt], fa[mt], fb, acc[mt]);
        }
        __syncthreads();
        if (nx) {
            sstore();
            __syncthreads();
        }
    }

    // epilogue: per-warp staging in sA (ldm=20)
    float* stg = sA + wid * 320;
    int row = lane >> 1, half = lane & 1;

#pragma unroll
    for (int mt = 0; mt < 4; mt++) {
        wmma::store_matrix_sync(stg, acc[mt], 20, wmma::mem_row_major);
        __syncwarp();
        int lr = wm + mt * 16 + row;
        if (m0 + lr < rows) {
            int ncol = wn + half * 8;
            const float* bb = &bias[(size_t)e * NT + n0 + ncol];
            const float* sp = &stg[row * 20 + half * 8];
            if (FFN1) {
                float4 v0, v1;
                v0.x = rna_tf32(fmaxf(sp[0] + bb[0], 0.f));
                v0.y = rna_tf32(fmaxf(sp[1] + bb[1], 0.f));
                v0.z = rna_tf32(fmaxf(sp[2] + bb[2], 0.f));
                v0.w = rna_tf32(fmaxf(sp[3] + bb[3], 0.f));
                v1.x = rna_tf32(fmaxf(sp[4] + bb[4], 0.f));
                v1.y = rna_tf32(fmaxf(sp[5] + bb[5], 0.f));
                v1.z = rna_tf32(fmaxf(sp[6] + bb[6], 0.f));
                v1.w = rna_tf32(fmaxf(sp[7] + bb[7], 0.f));
                float* dst = &g_H[(size_t)(base + m0 + lr) * FFN + n0 + ncol];
                *reinterpret_cast<float4*>(dst) = v0;
                *reinterpret_cast<float4*>(dst + 4) = v1;
            } else {
                float w = swt[lr];
                float* yp = &y[(size_t)stok[lr] * DMODEL + n0 + ncol];
#pragma unroll
                for (int j = 0; j < 8; j++)
                    atomicAdd(&yp[j], (sp[j] + bb[j]) * w);
            }
        }
        __syncwarp();
    }
}

// ================= FFMA fallback path (runs iff g_useMMA == 0) =================
__global__ void __launch_bounds__(256) k_f1(const float* __restrict__ x,
                                            const float* __restrict__ W1,
                                            const float* __restrict__ b1) {
    if (g_useMMA) return;
    int e = blockIdx.z;
    int rows = g_cnt[e];
    int m0 = blockIdx.x * BM;
    if (m0 >= rows) return;
    int n0 = blockIdx.y * 64;
    int base = g_off[e];

    __shared__ float As[16][BM + 4];
    __shared__ float Bs[16][64];
    __shared__ int   stok[BM];

    int tid = threadIdx.x;
    if (tid < BM) {
        int r = m0 + tid;
        stok[tid] = g_pairTok[base + (r < rows ? r : 0)];
    }
    __syncthreads();

    float acc[8][4];
#pragma unroll
    for (int i = 0; i < 8; i++)
#pragma unroll
        for (int j = 0; j < 4; j++) acc[i][j] = 0.f;

    const float* Wp = W1 + (size_t)e * DMODEL * FFN;
    int ty = tid >> 4, tx = tid & 15;

    for (int k0 = 0; k0 < DMODEL; k0 += 16) {
#pragma unroll
        for (int i = 0; i < 2; i++) {
            int idx = tid + i * 256;
            int r = idx >> 2;
            int c4 = (idx & 3) << 2;
            float4 v = *reinterpret_cast<const float4*>(&x[(size_t)stok[r] * DMODEL + k0 + c4]);
            As[c4 + 0][r] = v.x; As[c4 + 1][r] = v.y; As[c4 + 2][r] = v.z; As[c4 + 3][r] = v.w;
        }
        {
            int r = tid >> 4;
            int c4 = (tid & 15) << 2;
            *reinterpret_cast<float4*>(&Bs[r][c4]) =
                *reinterpret_cast<const float4*>(&Wp[(size_t)(k0 + r) * FFN + n0 + c4]);
        }
        __syncthreads();
#pragma unroll
        for (int k = 0; k < 16; k++) {
            float a[8], b[4];
            *reinterpret_cast<float4*>(a)     = *reinterpret_cast<float4*>(&As[k][ty * 8]);
            *reinterpret_cast<float4*>(a + 4) = *reinterpret_cast<float4*>(&As[k][ty * 8 + 4]);
            *reinterpret_cast<float4*>(b)     = *reinterpret_cast<float4*>(&Bs[k][tx * 4]);
#pragma unroll
            for (int i = 0; i < 8; i++)
#pragma unroll
                for (int j = 0; j < 4; j++) acc[i][j] += a[i] * b[j];
        }
        __syncthreads();
    }

    int n = n0 + tx * 4;
    float4 bb = *reinterpret_cast<const float4*>(&b1[(size_t)e * FFN + n]);
#pragma unroll
    for (int i = 0; i < 8; i++) {
        int gm = m0 + ty * 8 + i;
        if (gm < rows) {
            float4 v;
            v.x = fmaxf(acc[i][0] + bb.x, 0.f);
            v.y = fmaxf(acc[i][1] + bb.y, 0.f);
            v.z = fmaxf(acc[i][2] + bb.z, 0.f);
            v.w = fmaxf(acc[i][3] + bb.w, 0.f);
            *reinterpret_cast<float4*>(&g_H[(size_t)(base + gm) * FFN + n]) = v;
        }
    }
}

__global__ void __launch_bounds__(256) k_f2(const float* __restrict__ W2,
                                            const float* __restrict__ b2,
                                            float* __restrict__ y) {
    if (g_useMMA) return;
    int e = blockIdx.z;
    int rows = g_cnt[e];
    int m0 = blockIdx.x * BM;
    if (m0 >= rows) return;
    int n0 = blockIdx.y * 64;
    int base = g_off[e];

    __shared__ float As[16][BM + 4];
    __shared__ float Bs[16][64];
    __shared__ int   stok[BM];
    __shared__ float sw[BM];

    int tid = threadIdx.x;
    if (tid < BM) {
        int r = m0 + tid;
        int rr = (r < rows ? r : 0);
        stok[tid] = g_pairTok[base + rr];
        sw[tid]   = g_pairW[base + rr];
    }
    __syncthreads();

    float acc[8][4];
#pragma unroll
    for (int i = 0; i < 8; i++)
#pragma unroll
        for (int j = 0; j < 4; j++) acc[i][j] = 0.f;

    const float* Wp = W2 + (size_t)e * FFN * DMODEL;
    int ty = tid >> 4, tx = tid & 15;

    for (int k0 = 0; k0 < FFN; k0 += 16) {
#pragma unroll
        for (int i = 0; i < 2; i++) {
            int idx = tid + i * 256;
            int r = idx >> 2;
            int c4 = (idx & 3) << 2;
            float4 v = *reinterpret_cast<const float4*>(
                &g_H[(size_t)(base + m0 + r) * FFN + k0 + c4]);
            As[c4 + 0][r] = v.x; As[c4 + 1][r] = v.y; As[c4 + 2][r] = v.z; As[c4 + 3][r] = v.w;
        }
        {
            int r = tid >> 4;
            int c4 = (tid & 15) << 2;
            *reinterpret_cast<float4*>(&Bs[r][c4]) =
                *reinterpret_cast<const float4*>(&Wp[(size_t)(k0 + r) * DMODEL + n0 + c4]);
        }
        __syncthreads();
#pragma unroll
        for (int k = 0; k < 16; k++) {
            float a[8], b[4];
            *reinterpret_cast<float4*>(a)     = *reinterpret_cast<float4*>(&As[k][ty * 8]);
            *reinterpret_cast<float4*>(a + 4) = *reinterpret_cast<float4*>(&As[k][ty * 8 + 4]);
            *reinterpret_cast<float4*>(b)     = *reinterpret_cast<float4*>(&Bs[k][tx * 4]);
#pragma unroll
            for (int i = 0; i < 8; i++)
#pragma unroll
                for (int j = 0; j < 4; j++) acc[i][j] += a[i] * b[j];
        }
        __syncthreads();
    }

    int n = n0 + tx * 4;
    float4 bb = *reinterpret_cast<const float4*>(&b2[(size_t)e * DMODEL + n]);
#pragma unroll
    for (int i = 0; i < 8; i++) {
        int gm = m0 + ty * 8 + i;
        if (gm < rows) {
            float w = sw[ty * 8 + i];
            int tok = stok[ty * 8 + i];
            float* yp = &y[(size_t)tok * DMODEL + n];
            atomicAdd(yp + 0, (acc[i][0] + bb.x) * w);
            atomicAdd(yp + 1, (acc[i][1] + bb.y) * w);
            atomicAdd(yp + 2, (acc[i][2] + bb.z) * w);
            atomicAdd(yp + 3, (acc[i][3] + bb.w) * w);
        }
    }
}

// ---------------- launch ----------------
extern "C" void kernel_launch(void* const* d_in, const int* in_sizes, int n_in,
                              void* d_out, int out_size) {
    const float* x  = (const float*)d_in[0];
    const float* Wr = (const float*)d_in[1];
    const float* W1 = (const float*)d_in[2];
    const float* b1 = (const float*)d_in[3];
    const float* W2 = (const float*)d_in[4];
    const float* b2 = (const float*)d_in[5];
    float* out = (float*)d_out;

    k_zero<<<2048, 256>>>(out);
    k_mmatest<<<1, 32>>>();
    k_router<<<NTOK / 8, 256>>>(x, Wr);
    k_finalize<<<1, 1024>>>(out);
    k_scatter<<<(NTOK + 255) / 256, 256>>>();

    // WMMA tf32 path (inert if self-test failed)
    k_wmma<DMODEL, true><<<dim3(NPAIR / BM, FFN / BN, NEXP), 256>>>(x, W1, b1, out);
    k_wmma<FFN, false><<<dim3(NPAIR / BM, DMODEL / BN, NEXP), 256>>>(x, W2, b2, out);

    // FFMA fallback path (inert if self-test passed)
    k_f1<<<dim3(NPAIR / BM, FFN / 64, NEXP), 256>>>(x, W1, b1);
    k_f2<<<dim3(NPAIR / BM, DMODEL / 64, NEXP), 256>>>(W2, b2, out);
}

// round 7
// speedup vs baseline: 1.8231x; 1.8231x over previous
#include <cuda_runtime.h>
#include <math.h>
#include <stdint.h>
#include <mma.h>

using namespace nvcuda;

#define NTOK 8192
#define DMODEL 1024
#define FFN 4096
#define NEXP 8
#define NPAIR (NTOK*2)
#define LB_COEF 0.01f
#define Z_COEF 0.001f

// GEMM tiling
#define BM 128
#define BN 128
#define BK 32
#define ASTR 36      // A smem row stride (floats)
#define BNSTR 132    // B smem row stride (floats)
#define A_STAGE (BM*ASTR)          // 4608 floats
#define B_STAGE (BK*BNSTR)         // 4224 floats
#define DYN_SMEM ((2*A_STAGE + 2*B_STAGE)*4)   // 70656 B

// ---------------- device scratch (keep ~R1 footprint; extra statics proven fatal) ----
__device__ float g_H[(size_t)(NPAIR + BM) * FFN];   // 268 MB hidden per pair slot
__device__ float g_probs[NTOK * NEXP];
__device__ float g_zsq[NTOK];
__device__ int   g_te[NTOK * 2];
__device__ float g_tw[NTOK * 2];
__device__ int   g_pairTok[NPAIR + BM];
__device__ float g_pairW[NPAIR + BM];
__device__ int   g_cnt[NEXP];
__device__ int   g_off[NEXP];
__device__ int   g_cursor[NEXP];

// ---------------- helpers ----------------
__device__ __forceinline__ float rna_tf32(float x) {
    float r; asm("cvt.rna.tf32.f32 %0, %1;" : "=f"(r) : "f"(x)); return r;
}
__device__ __forceinline__ uint32_t s2u(const void* p) {
    uint32_t a;
    asm("{ .reg .u64 t; cvta.to.shared.u64 t, %1; cvt.u32.u64 %0, t; }" : "=r"(a) : "l"(p));
    return a;
}
__device__ __forceinline__ void cp16(uint32_t dst, const void* src) {
    asm volatile("cp.async.cg.shared.global [%0], [%1], 16;" :: "r"(dst), "l"(src));
}
__device__ __forceinline__ void cp_commit() {
    asm volatile("cp.async.commit_group;" ::: "memory");
}
template<int N>
__device__ __forceinline__ void cp_wait() {
    asm volatile("cp.async.wait_group %0;" :: "n"(N) : "memory");
}

// ---------------- kernel 0: zero y + counters ----------------
__global__ void k_zero(float* __restrict__ y) {
    size_t i = (size_t)blockIdx.x * blockDim.x + threadIdx.x;
    const size_t n4 = (size_t)NTOK * DMODEL / 4;
    float4 z = make_float4(0.f, 0.f, 0.f, 0.f);
    for (; i < n4; i += (size_t)gridDim.x * blockDim.x)
        reinterpret_cast<float4*>(y)[i] = z;
    if (blockIdx.x == 0 && threadIdx.x < NEXP) g_cnt[threadIdx.x] = 0;
}

// ---------------- kernel 1: router ----------------
__global__ void __launch_bounds__(256) k_router(const float* __restrict__ x,
                                                const float* __restrict__ Wr) {
    __shared__ float sWr[DMODEL * NEXP];
    int tid = threadIdx.x;
    for (int i = tid * 4; i < DMODEL * NEXP; i += blockDim.x * 4)
        *reinterpret_cast<float4*>(&sWr[i]) = *reinterpret_cast<const float4*>(&Wr[i]);
    __syncthreads();

    int warp = tid >> 5, lane = tid & 31;
    int t = blockIdx.x * 8 + warp;
    if (t >= NTOK) return;

    float acc[NEXP];
#pragma unroll
    for (int e = 0; e < NEXP; e++) acc[e] = 0.f;
    const float* xr = x + (size_t)t * DMODEL;
    for (int d = lane; d < DMODEL; d += 32) {
        float xv = xr[d];
#pragma unroll
        for (int e = 0; e < NEXP; e++) acc[e] += xv * sWr[d * NEXP + e];
    }
#pragma unroll
    for (int e = 0; e < NEXP; e++)
        for (int o = 16; o; o >>= 1) acc[e] += __shfl_xor_sync(0xffffffff, acc[e], o);

    if (lane == 0) {
        float v0 = -1e30f; int i0 = 0;
#pragma unroll
        for (int e = 0; e < NEXP; e++) if (acc[e] > v0) { v0 = acc[e]; i0 = e; }
        float v1 = -1e30f; int i1 = 0;
#pragma unroll
        for (int e = 0; e < NEXP; e++) if (e != i0 && acc[e] > v1) { v1 = acc[e]; i1 = e; }

        float e1v = expf(v1 - v0);
        float inv2 = 1.f / (1.f + e1v);

        float se = 0.f, pr[NEXP];
#pragma unroll
        for (int e = 0; e < NEXP; e++) { pr[e] = expf(acc[e] - v0); se += pr[e]; }
        float invs = 1.f / se;
#pragma unroll
        for (int e = 0; e < NEXP; e++) g_probs[t * NEXP + e] = pr[e] * invs;
        float z = v0 + logf(se);
        g_zsq[t] = z * z;

        g_te[t * 2] = i0; g_te[t * 2 + 1] = i1;
        g_tw[t * 2] = inv2; g_tw[t * 2 + 1] = e1v * inv2;
        atomicAdd(&g_cnt[i0], 1);
        atomicAdd(&g_cnt[i1], 1);
    }
}

// ---------------- kernel 2: reductions + aux + offsets ----------------
__global__ void __launch_bounds__(1024) k_finalize(float* __restrict__ out) {
    __shared__ float red[1024];
    __shared__ float simp[NEXP];
    __shared__ float szsq;
    int tid = threadIdx.x;

    float s[NEXP];
#pragma unroll
    for (int e = 0; e < NEXP; e++) s[e] = 0.f;
    float zs = 0.f;
    for (int t = tid; t < NTOK; t += 1024) {
#pragma unroll
        for (int e = 0; e < NEXP; e++) s[e] += g_probs[t * NEXP + e];
        zs += g_zsq[t];
    }
    for (int e = 0; e < NEXP; e++) {
        red[tid] = s[e]; __syncthreads();
        for (int o = 512; o > 0; o >>= 1) { if (tid < o) red[tid] += red[tid + o]; __syncthreads(); }
        if (tid == 0) simp[e] = red[0] / (float)NTOK;
        __syncthreads();
    }
    red[tid] = zs; __syncthreads();
    for (int o = 512; o > 0; o >>= 1) { if (tid < o) red[tid] += red[tid + o]; __syncthreads(); }
    if (tid == 0) szsq = red[0];
    __syncthreads();

    if (tid == 0) {
        float lb = 0.f;
#pragma unroll
        for (int e = 0; e < NEXP; e++) lb += simp[e] * simp[e];
        lb *= (float)NEXP * LB_COEF;
        float aux = lb + (szsq / (float)NTOK) * Z_COEF;

        float* tail = out + (size_t)NTOK * DMODEL;
        int tot = 0;
        for (int e = 0; e < NEXP; e++) tot += g_cnt[e];
        float denom = fmaxf((float)tot, 1.f);
        for (int e = 0; e < NEXP; e++) {
            tail[e] = (float)g_cnt[e];
            tail[NEXP + e] = (float)g_cnt[e] / denom;
        }
        tail[2 * NEXP] = aux;

        int o = 0;
        for (int e = 0; e < NEXP; e++) { g_off[e] = o; g_cursor[e] = o; o += g_cnt[e]; }
    }
}

// ---------------- kernel 3: scatter ----------------
__global__ void k_scatter() {
    int t = blockIdx.x * blockDim.x + threadIdx.x;
    if (t >= NTOK) return;
#pragma unroll
    for (int k = 0; k < 2; k++) {
        int e = g_te[t * 2 + k];
        int p = atomicAdd(&g_cursor[e], 1);
        g_pairTok[p] = t;
        g_pairW[p] = g_tw[t * 2 + k];
    }
}

// ---------------- WMMA tf32 grouped GEMM, cp.async 2-stage ----------------
// FFN1: H = relu(gather(x) @ W1[e] + b1)   W1[e]: [D][F] row-major [k][n]
// else: y += w * (H @ W2[e] + b2)          W2[e]: [F][D] row-major [k][n]
template<int KDIM, bool FFN1>
__global__ void __launch_bounds__(256) k_wmma(const float* __restrict__ x,
                                              const float* __restrict__ W,
                                              const float* __restrict__ bias,
                                              float* __restrict__ y) {
    int e = blockIdx.z;
    int rows = g_cnt[e];
    int m0 = blockIdx.x * BM;
    if (m0 >= rows) return;
    int base = g_off[e];
    int n0 = blockIdx.y * BN;
    const int NT = FFN1 ? FFN : DMODEL;

    extern __shared__ __align__(16) float sm[];
    float* sA = sm;                       // [2][BM][ASTR]
    float* sB = sm + 2 * A_STAGE;         // [2][BK][BNSTR]
    __shared__ int   stok[BM];
    __shared__ float swt[BM];

    int tid = threadIdx.x;
    if (tid < BM) {
        int r = m0 + tid;
        int rr = (r < rows) ? r : 0;
        stok[tid] = g_pairTok[base + rr];
        swt[tid]  = g_pairW[base + rr];
    }
    __syncthreads();

    const float* We = W + (size_t)e * ((size_t)DMODEL * FFN);

    // per-thread loop-invariant source pointers (k0 added per chunk)
    const float* srcA[4];
    uint32_t dstA[4];
#pragma unroll
    for (int j = 0; j < 4; j++) {
        int idx = tid + j * 256;
        int r = idx >> 3, c4 = (idx & 7) * 4;          // r<128, c4<32
        srcA[j] = FFN1 ? (x + (size_t)stok[r] * DMODEL + c4)
                       : (g_H + (size_t)(base + m0 + r) * KDIM + c4);
        dstA[j] = s2u(&sA[r * ASTR + c4]);
    }
    const float* srcB[4];
    uint32_t dstB[4];
#pragma unroll
    for (int j = 0; j < 4; j++) {
        int idx = tid + j * 256;
        int r = idx >> 5, c4 = (idx & 31) * 4;         // r<32 (k), c4<128 (n)
        srcB[j] = We + (size_t)r * NT + n0 + c4;
        dstB[j] = s2u(&sB[r * BNSTR + c4]);
    }

    const int nch = KDIM / BK;

    auto load_stage = [&](int c, int s) {
        int k0 = c * BK;
        uint32_t ao = (uint32_t)(s * A_STAGE) * 4;
        uint32_t bo = (uint32_t)(s * B_STAGE) * 4;
#pragma unroll
        for (int j = 0; j < 4; j++) cp16(dstA[j] + ao, srcA[j] + k0);
#pragma unroll
        for (int j = 0; j < 4; j++) cp16(dstB[j] + bo, srcB[j] + (size_t)k0 * NT);
        cp_commit();
    };

    load_stage(0, 0);
    load_stage(1, 1);

    int lane = tid & 31, wid = tid >> 5;
    int wm = (wid & 1) * 64;      // 2 warps over M (64 each)
    int wn = (wid >> 1) * 32;     // 4 warps over N (32 each)

    wmma::fragment<wmma::accumulator, 16, 16, 8, float> acc[4][2];
#pragma unroll
    for (int mt = 0; mt < 4; mt++)
#pragma unroll
        for (int nt = 0; nt < 2; nt++) wmma::fill_fragment(acc[mt][nt], 0.f);

    for (int c = 0; c < nch; c++) {
        int s = c & 1;
        cp_wait<1>();
        __syncthreads();
        const float* fAp = sA + s * A_STAGE;
        const float* fBp = sB + s * B_STAGE;
#pragma unroll
        for (int kk = 0; kk < BK; kk += 8) {
            wmma::fragment<wmma::matrix_a, 16, 16, 8, wmma::precision::tf32,
                           wmma::row_major> fa[4];
            wmma::fragment<wmma::matrix_b, 16, 16, 8, wmma::precision::tf32,
                           wmma::row_major> fb[2];
#pragma unroll
            for (int mt = 0; mt < 4; mt++) {
                wmma::load_matrix_sync(fa[mt], &fAp[(wm + mt * 16) * ASTR + kk], ASTR);
                if (FFN1) {   // x unrounded -> RNA in fragment; H pre-rounded -> skip
#pragma unroll
                    for (int q = 0; q < fa[mt].num_elements; q++)
                        fa[mt].x[q] = rna_tf32(fa[mt].x[q]);
                }
            }
#pragma unroll
            for (int nt = 0; nt < 2; nt++) {
                wmma::load_matrix_sync(fb[nt], &fBp[kk * BNSTR + wn + nt * 16], BNSTR);
#pragma unroll
                for (int q = 0; q < fb[nt].num_elements; q++)
                    fb[nt].x[q] = rna_tf32(fb[nt].x[q]);
            }
#pragma unroll
            for (int mt = 0; mt < 4; mt++)
#pragma unroll
                for (int nt = 0; nt < 2; nt++)
                    wmma::mma_sync(acc[mt][nt], fa[mt], fb[nt], acc[mt][nt]);
        }
        __syncthreads();
        if (c + 2 < nch) load_stage(c + 2, s);
        else cp_commit();   // empty group keeps wait<1> draining correctly
    }

    // ---------------- epilogue: per-warp staging (ldm=20) ----------------
    float* stg = sm + wid * 320;
    int row = lane >> 1, half = lane & 1;

#pragma unroll
    for (int mt = 0; mt < 4; mt++) {
#pragma unroll
        for (int nt = 0; nt < 2; nt++) {
            wmma::store_matrix_sync(stg, acc[mt][nt], 20, wmma::mem_row_major);
            __syncwarp();
            int lr = wm + mt * 16 + row;
            if (m0 + lr < rows) {
                int ncol = wn + nt * 16 + half * 8;
                const float* bb = &bias[(size_t)e * NT + n0 + ncol];
                const float* sp = &stg[row * 20 + half * 8];
                if (FFN1) {
                    float4 v0, v1;
                    v0.x = rna_tf32(fmaxf(sp[0] + bb[0], 0.f));
                    v0.y = rna_tf32(fmaxf(sp[1] + bb[1], 0.f));
                    v0.z = rna_tf32(fmaxf(sp[2] + bb[2], 0.f));
                    v0.w = rna_tf32(fmaxf(sp[3] + bb[3], 0.f));
                    v1.x = rna_tf32(fmaxf(sp[4] + bb[4], 0.f));
                    v1.y = rna_tf32(fmaxf(sp[5] + bb[5], 0.f));
                    v1.z = rna_tf32(fmaxf(sp[6] + bb[6], 0.f));
                    v1.w = rna_tf32(fmaxf(sp[7] + bb[7], 0.f));
                    float* dst = &g_H[(size_t)(base + m0 + lr) * FFN + n0 + ncol];
                    *reinterpret_cast<float4*>(dst) = v0;
                    *reinterpret_cast<float4*>(dst + 4) = v1;
                } else {
                    float w = swt[lr];
                    float* yp = &y[(size_t)stok[lr] * DMODEL + n0 + ncol];
#pragma unroll
                    for (int j = 0; j < 8; j++)
                        atomicAdd(&yp[j], (sp[j] + bb[j]) * w);
                }
            }
            __syncwarp();
        }
    }
}

// ---------------- launch ----------------
extern "C" void kernel_launch(void* const* d_in, const int* in_sizes, int n_in,
                              void* d_out, int out_size) {
    const float* x  = (const float*)d_in[0];
    const float* Wr = (const float*)d_in[1];
    const float* W1 = (const float*)d_in[2];
    const float* b1 = (const float*)d_in[3];
    const float* W2 = (const float*)d_in[4];
    const float* b2 = (const float*)d_in[5];
    float* out = (float*)d_out;

    static int smem_set = 0;
    if (!smem_set) {
        cudaFuncSetAttribute(k_wmma<DMODEL, true>,
                             cudaFuncAttributeMaxDynamicSharedMemorySize, DYN_SMEM);
        cudaFuncSetAttribute(k_wmma<FFN, false>,
                             cudaFuncAttributeMaxDynamicSharedMemorySize, DYN_SMEM);
        smem_set = 1;
    }

    k_zero<<<2048, 256>>>(out);
    k_router<<<NTOK / 8, 256>>>(x, Wr);
    k_finalize<<<1, 1024>>>(out);
    k_scatter<<<(NTOK + 255) / 256, 256>>>();

    k_wmma<DMODEL, true><<<dim3(NPAIR / BM, FFN / BN, NEXP), 256, DYN_SMEM>>>(x, W1, b1, out);
    k_wmma<FFN, false><<<dim3(NPAIR / BM, DMODEL / BN, NEXP), 256, DYN_SMEM>>>(x, W2, b2, out);
}

// round 8
// speedup vs baseline: 6.2491x; 3.4278x over previous
#include <cuda_runtime.h>
#include <math.h>
#include <stdint.h>
#include <cuda_fp16.h>
#include <mma.h>

using namespace nvcuda;

#define NTOK 8192
#define DMODEL 1024
#define FFN 4096
#define NEXP 8
#define NPAIR (NTOK*2)
#define LB_COEF 0.01f
#define Z_COEF 0.001f

// GEMM tiling
#define BM 128
#define BN 128
#define BK 32
#define ASTR 40      // A smem row stride in halves (80B, mult of 8)
#define BSTR 136     // B smem row stride in halves (272B, mult of 8)
#define A_STAGE (BM*ASTR)    // halves
#define B_STAGE (BK*BSTR)    // halves

// ---------------- device scratch (total ~134 MB; large statics proven fatal) ----
__device__ __half g_H[(size_t)(NPAIR + BM) * FFN];   // hidden, fp16
__device__ float g_probs[NTOK * NEXP];
__device__ float g_zsq[NTOK];
__device__ int   g_te[NTOK * 2];
__device__ float g_tw[NTOK * 2];
__device__ int   g_pairTok[NPAIR + BM];
__device__ float g_pairW[NPAIR + BM];
__device__ int   g_cnt[NEXP];
__device__ int   g_off[NEXP];
__device__ int   g_cursor[NEXP];

// ---------------- kernel 0: zero y + counters ----------------
__global__ void k_zero(float* __restrict__ y) {
    size_t i = (size_t)blockIdx.x * blockDim.x + threadIdx.x;
    const size_t n4 = (size_t)NTOK * DMODEL / 4;
    float4 z = make_float4(0.f, 0.f, 0.f, 0.f);
    for (; i < n4; i += (size_t)gridDim.x * blockDim.x)
        reinterpret_cast<float4*>(y)[i] = z;
    if (blockIdx.x == 0 && threadIdx.x < NEXP) g_cnt[threadIdx.x] = 0;
}

// ---------------- kernel 1: router (exact fp32; expert choice must not flip) ----
__global__ void __launch_bounds__(256) k_router(const float* __restrict__ x,
                                                const float* __restrict__ Wr) {
    __shared__ float sWr[DMODEL * NEXP];
    int tid = threadIdx.x;
    for (int i = tid * 4; i < DMODEL * NEXP; i += blockDim.x * 4)
        *reinterpret_cast<float4*>(&sWr[i]) = *reinterpret_cast<const float4*>(&Wr[i]);
    __syncthreads();

    int warp = tid >> 5, lane = tid & 31;
    int t = blockIdx.x * 8 + warp;
    if (t >= NTOK) return;

    float acc[NEXP];
#pragma unroll
    for (int e = 0; e < NEXP; e++) acc[e] = 0.f;
    const float* xr = x + (size_t)t * DMODEL;
    for (int d = lane; d < DMODEL; d += 32) {
        float xv = xr[d];
#pragma unroll
        for (int e = 0; e < NEXP; e++) acc[e] += xv * sWr[d * NEXP + e];
    }
#pragma unroll
    for (int e = 0; e < NEXP; e++)
        for (int o = 16; o; o >>= 1) acc[e] += __shfl_xor_sync(0xffffffff, acc[e], o);

    if (lane == 0) {
        float v0 = -1e30f; int i0 = 0;
#pragma unroll
        for (int e = 0; e < NEXP; e++) if (acc[e] > v0) { v0 = acc[e]; i0 = e; }
        float v1 = -1e30f; int i1 = 0;
#pragma unroll
        for (int e = 0; e < NEXP; e++) if (e != i0 && acc[e] > v1) { v1 = acc[e]; i1 = e; }

        float e1v = expf(v1 - v0);
        float inv2 = 1.f / (1.f + e1v);

        float se = 0.f, pr[NEXP];
#pragma unroll
        for (int e = 0; e < NEXP; e++) { pr[e] = expf(acc[e] - v0); se += pr[e]; }
        float invs = 1.f / se;
#pragma unroll
        for (int e = 0; e < NEXP; e++) g_probs[t * NEXP + e] = pr[e] * invs;
        float z = v0 + logf(se);
        g_zsq[t] = z * z;

        g_te[t * 2] = i0; g_te[t * 2 + 1] = i1;
        g_tw[t * 2] = inv2; g_tw[t * 2 + 1] = e1v * inv2;
        atomicAdd(&g_cnt[i0], 1);
        atomicAdd(&g_cnt[i1], 1);
    }
}

// ---------------- kernel 2: reductions + aux + offsets ----------------
__global__ void __launch_bounds__(1024) k_finalize(float* __restrict__ out) {
    __shared__ float red[1024];
    __shared__ float simp[NEXP];
    __shared__ float szsq;
    int tid = threadIdx.x;

    float s[NEXP];
#pragma unroll
    for (int e = 0; e < NEXP; e++) s[e] = 0.f;
    float zs = 0.f;
    for (int t = tid; t < NTOK; t += 1024) {
#pragma unroll
        for (int e = 0; e < NEXP; e++) s[e] += g_probs[t * NEXP + e];
        zs += g_zsq[t];
    }
    for (int e = 0; e < NEXP; e++) {
        red[tid] = s[e]; __syncthreads();
        for (int o = 512; o > 0; o >>= 1) { if (tid < o) red[tid] += red[tid + o]; __syncthreads(); }
        if (tid == 0) simp[e] = red[0] / (float)NTOK;
        __syncthreads();
    }
    red[tid] = zs; __syncthreads();
    for (int o = 512; o > 0; o >>= 1) { if (tid < o) red[tid] += red[tid + o]; __syncthreads(); }
    if (tid == 0) szsq = red[0];
    __syncthreads();

    if (tid == 0) {
        float lb = 0.f;
#pragma unroll
        for (int e = 0; e < NEXP; e++) lb += simp[e] * simp[e];
        lb *= (float)NEXP * LB_COEF;
        float aux = lb + (szsq / (float)NTOK) * Z_COEF;

        float* tail = out + (size_t)NTOK * DMODEL;
        int tot = 0;
        for (int e = 0; e < NEXP; e++) tot += g_cnt[e];
        float denom = fmaxf((float)tot, 1.f);
        for (int e = 0; e < NEXP; e++) {
            tail[e] = (float)g_cnt[e];
            tail[NEXP + e] = (float)g_cnt[e] / denom;
        }
        tail[2 * NEXP] = aux;

        int o = 0;
        for (int e = 0; e < NEXP; e++) { g_off[e] = o; g_cursor[e] = o; o += g_cnt[e]; }
    }
}

// ---------------- kernel 3: scatter ----------------
__global__ void k_scatter() {
    int t = blockIdx.x * blockDim.x + threadIdx.x;
    if (t >= NTOK) return;
#pragma unroll
    for (int k = 0; k < 2; k++) {
        int e = g_te[t * 2 + k];
        int p = atomicAdd(&g_cursor[e], 1);
        g_pairTok[p] = t;
        g_pairW[p] = g_tw[t * 2 + k];
    }
}

// ---------------- fp16 WMMA grouped GEMM, reg-prefetch double buffer ----------------
// FFN1: H = relu_f16(gather(x) @ W1[e] + b1)   W1[e]: [D][F] row-major [k][n]
// else: y += w * (H @ W2[e] + b2)              W2[e]: [F][D] row-major [k][n]
template<int KDIM, bool FFN1>
__global__ void __launch_bounds__(256) k_wmma(const float* __restrict__ x,
                                              const float* __restrict__ W,
                                              const float* __restrict__ bias,
                                              float* __restrict__ y) {
    int e = blockIdx.z;
    int rows = g_cnt[e];
    int m0 = blockIdx.x * BM;
    if (m0 >= rows) return;
    int base = g_off[e];
    int n0 = blockIdx.y * BN;
    const int NT = FFN1 ? FFN : DMODEL;

    __shared__ __align__(16) __half sA[2 * A_STAGE];   // 20480 B
    __shared__ __align__(16) __half sB[2 * B_STAGE];   // 17408 B
    __shared__ int   stok[BM];
    __shared__ float swt[BM];

    int tid = threadIdx.x;
    if (tid < BM) {
        int r = m0 + tid;
        int rr = (r < rows) ? r : 0;
        stok[tid] = g_pairTok[base + rr];
        swt[tid]  = g_pairW[base + rr];
    }
    __syncthreads();

    const float* We = W + (size_t)e * ((size_t)DMODEL * FFN);

    // prefetch registers
    float4 pAf[4];   // FFN1: A as fp32 (x rows)
    uint4  pAh[2];   // GEMM2: A as fp16 (g_H rows)
    float4 pBf[4];   // B always fp32 weights

    // ---- loaders ----
    auto gloadA = [&](int c) {
        int k0 = c * BK;
        if (FFN1) {
#pragma unroll
            for (int j = 0; j < 4; j++) {
                int idx = tid + j * 256;
                int r = idx >> 3, c4 = (idx & 7) * 4;
                pAf[j] = *reinterpret_cast<const float4*>(
                    &x[(size_t)stok[r] * DMODEL + k0 + c4]);
            }
        } else {
#pragma unroll
            for (int j = 0; j < 2; j++) {
                int idx = tid + j * 256;
                int r = idx >> 2, c8 = (idx & 3) * 8;
                pAh[j] = *reinterpret_cast<const uint4*>(
                    &g_H[(size_t)(base + m0 + r) * KDIM + k0 + c8]);
            }
        }
    };
    auto gloadB = [&](int c) {
        int k0 = c * BK;
#pragma unroll
        for (int j = 0; j < 4; j++) {
            int idx = tid + j * 256;
            int r = idx >> 5, cn = (idx & 31) * 4;
            pBf[j] = *reinterpret_cast<const float4*>(
                &We[(size_t)(k0 + r) * NT + n0 + cn]);
        }
    };
    auto sstore = [&](int s) {
        __half* a = sA + s * A_STAGE;
        __half* b = sB + s * B_STAGE;
        if (FFN1) {
#pragma unroll
            for (int j = 0; j < 4; j++) {
                int idx = tid + j * 256;
                int r = idx >> 3, c4 = (idx & 7) * 4;
                __half2 h0 = __floats2half2_rn(pAf[j].x, pAf[j].y);
                __half2 h1 = __floats2half2_rn(pAf[j].z, pAf[j].w);
                *reinterpret_cast<__half2*>(&a[r * ASTR + c4])     = h0;
                *reinterpret_cast<__half2*>(&a[r * ASTR + c4 + 2]) = h1;
            }
        } else {
#pragma unroll
            for (int j = 0; j < 2; j++) {
                int idx = tid + j * 256;
                int r = idx >> 2, c8 = (idx & 3) * 8;
                *reinterpret_cast<uint4*>(&a[r * ASTR + c8]) = pAh[j];
            }
        }
#pragma unroll
        for (int j = 0; j < 4; j++) {
            int idx = tid + j * 256;
            int r = idx >> 5, cn = (idx & 31) * 4;
            __half2 h0 = __floats2half2_rn(pBf[j].x, pBf[j].y);
            __half2 h1 = __floats2half2_rn(pBf[j].z, pBf[j].w);
            *reinterpret_cast<__half2*>(&b[r * BSTR + cn])     = h0;
            *reinterpret_cast<__half2*>(&b[r * BSTR + cn + 2]) = h1;
        }
    };

    int lane = tid & 31, wid = tid >> 5;
    int wm = (wid & 1) * 64;      // 2 warps over M (64 each)
    int wn = (wid >> 1) * 32;     // 4 warps over N (32 each)

    wmma::fragment<wmma::accumulator, 16, 16, 16, float> acc[4][2];
#pragma unroll
    for (int mt = 0; mt < 4; mt++)
#pragma unroll
        for (int nt = 0; nt < 2; nt++) wmma::fill_fragment(acc[mt][nt], 0.f);

    const int nch = KDIM / BK;

    gloadA(0); gloadB(0);
    sstore(0);
    gloadA(1); gloadB(1);
    __syncthreads();

    int s = 0;
    for (int c = 0; c < nch; c++) {
        const __half* fAp = sA + s * A_STAGE;
        const __half* fBp = sB + s * B_STAGE;
#pragma unroll
        for (int kk = 0; kk < BK / 16; kk++) {
            wmma::fragment<wmma::matrix_a, 16, 16, 16, __half, wmma::row_major> fa[4];
            wmma::fragment<wmma::matrix_b, 16, 16, 16, __half, wmma::row_major> fb[2];
#pragma unroll
            for (int mt = 0; mt < 4; mt++)
                wmma::load_matrix_sync(fa[mt], &fAp[(wm + mt * 16) * ASTR + kk * 16], ASTR);
#pragma unroll
            for (int nt = 0; nt < 2; nt++)
                wmma::load_matrix_sync(fb[nt], &fBp[kk * 16 * BSTR + wn + nt * 16], BSTR);
#pragma unroll
            for (int mt = 0; mt < 4; mt++)
#pragma unroll
                for (int nt = 0; nt < 2; nt++)
                    wmma::mma_sync(acc[mt][nt], fa[mt], fb[nt], acc[mt][nt]);
        }
        if (c + 1 < nch) {
            sstore(s ^ 1);
            if (c + 2 < nch) { gloadA(c + 2); gloadB(c + 2); }
        }
        __syncthreads();
        s ^= 1;
    }

    // ---------------- epilogue: per-warp staging over sA (ldm=20) ----------------
    float* stg = reinterpret_cast<float*>(sA) + wid * 320;
    int row = lane >> 1, half = lane & 1;

#pragma unroll
    for (int mt = 0; mt < 4; mt++) {
#pragma unroll
        for (int nt = 0; nt < 2; nt++) {
            wmma::store_matrix_sync(stg, acc[mt][nt], 20, wmma::mem_row_major);
            __syncwarp();
            int lr = wm + mt * 16 + row;
            if (m0 + lr < rows) {
                int ncol = wn + nt * 16 + half * 8;
                const float* bb = &bias[(size_t)e * NT + n0 + ncol];
                const float* sp = &stg[row * 20 + half * 8];
                if (FFN1) {
                    __half2 h[4];
#pragma unroll
                    for (int q = 0; q < 4; q++)
                        h[q] = __floats2half2_rn(fmaxf(sp[2*q] + bb[2*q], 0.f),
                                                 fmaxf(sp[2*q+1] + bb[2*q+1], 0.f));
                    *reinterpret_cast<uint4*>(
                        &g_H[(size_t)(base + m0 + lr) * FFN + n0 + ncol]) =
                        *reinterpret_cast<uint4*>(h);
                } else {
                    float w = swt[lr];
                    float* yp = &y[(size_t)stok[lr] * DMODEL + n0 + ncol];
#pragma unroll
                    for (int j = 0; j < 8; j++)
                        atomicAdd(&yp[j], (sp[j] + bb[j]) * w);
                }
            }
            __syncwarp();
        }
    }
}

// ---------------- launch ----------------
extern "C" void kernel_launch(void* const* d_in, const int* in_sizes, int n_in,
                              void* d_out, int out_size) {
    const float* x  = (const float*)d_in[0];
    const float* Wr = (const float*)d_in[1];
    const float* W1 = (const float*)d_in[2];
    const float* b1 = (const float*)d_in[3];
    const float* W2 = (const float*)d_in[4];
    const float* b2 = (const float*)d_in[5];
    float* out = (float*)d_out;

    k_zero<<<2048, 256>>>(out);
    k_router<<<NTOK / 8, 256>>>(x, Wr);
    k_finalize<<<1, 1024>>>(out);
    k_scatter<<<(NTOK + 255) / 256, 256>>>();

    k_wmma<DMODEL, true><<<dim3(NPAIR / BM, FFN / BN, NEXP), 256>>>(x, W1, b1, out);
    k_wmma<FFN, false><<<dim3(NPAIR / BM, DMODEL / BN, NEXP), 256>>>(x, W2, b2, out);
}